// round 13
// baseline (speedup 1.0000x reference)
#include <cuda_runtime.h>
#include <cuda_fp16.h>
#include <math.h>
#include <stdint.h>

// Problem constants
#define MDIM 16384          // B*N = 2*8192 rows
#define EDIM 1024           // embed
#define DH   64             // head dim
#define NCH  64             // chunks per sequence (8192/128)
#define BHN  32             // B*H
#define QKVN 3072           // fused projection width

// ---------------- scratch (device globals) ----------------------------------
__device__ __half hX[MDIM * EDIM];
__device__ __half hWqkv[EDIM * QKVN];     // [k][n] concat Wq|Wk|Wv
__device__ __half hWo[EDIM * EDIM];       // [k][n]
__device__ __half hWg1[EDIM * DH];        // [k][n]
__device__ __half hWg2[DH * EDIM];        // [k][n]
__device__ __half hQKV[MDIM * QKVN];      // fused silu(xW) outputs
__device__ __half hG1[MDIM * DH];
__device__ __half hGATE[MDIM * EDIM];
__device__ __half hO[MDIM * EDIM];
__device__ __half hOLN[MDIM * EDIM];
__device__ float gM[BHN * NCH * DH * DH];
__device__ float gKV[BHN * NCH * DH * DH];

// ---------------- streams/events for graph fork-join (created at load) ------
static cudaStream_t g_s1 = nullptr;
static cudaEvent_t g_evFork = nullptr, g_evW = nullptr, g_evX = nullptr,
                   g_evGate = nullptr;
namespace {
struct StreamInit {
    StreamInit() {
        cudaStreamCreateWithFlags(&g_s1, cudaStreamNonBlocking);
        cudaEventCreateWithFlags(&g_evFork, cudaEventDisableTiming);
        cudaEventCreateWithFlags(&g_evW, cudaEventDisableTiming);
        cudaEventCreateWithFlags(&g_evX, cudaEventDisableTiming);
        cudaEventCreateWithFlags(&g_evGate, cudaEventDisableTiming);
    }
};
StreamInit g_stream_init;
}

__device__ __forceinline__ float head_slope(int h) {
    return exp2f(-0.5f * (float)(h + 1)) * 1.00001f;
}

template <int EPI>
__device__ __forceinline__ float epilogue(float v) {
    if (EPI == 1) {                       // silu (fast-math)
        const float e = __expf(-v);
        return __fdividef(v, 1.f + e);
    }
    if (EPI == 2) {                       // sigmoid (fast-math)
        const float e = __expf(-v);
        return __fdividef(1.f, 1.f + e);
    }
    return v;
}

#define MMA_F16(acc, a0, a1, a2, a3, b0, b1) \
    asm volatile( \
        "mma.sync.aligned.m16n8k16.row.col.f32.f16.f16.f32 " \
        "{%0,%1,%2,%3}, {%4,%5,%6,%7}, {%8,%9}, {%0,%1,%2,%3};\n" \
        : "+f"((acc)[0]), "+f"((acc)[1]), "+f"((acc)[2]), "+f"((acc)[3]) \
        : "r"(a0), "r"(a1), "r"(a2), "r"(a3), "r"(b0), "r"(b1))

#define LDSM_X4(r, addr) \
    asm volatile("ldmatrix.sync.aligned.m8n8.x4.shared.b16 {%0,%1,%2,%3}, [%4];" \
        : "=r"((r)[0]), "=r"((r)[1]), "=r"((r)[2]), "=r"((r)[3]) : "r"(addr))
#define LDSM_X2(r, addr) \
    asm volatile("ldmatrix.sync.aligned.m8n8.x2.shared.b16 {%0,%1}, [%2];" \
        : "=r"((r)[0]), "=r"((r)[1]) : "r"(addr))
#define LDSM_X4T(r, addr) \
    asm volatile("ldmatrix.sync.aligned.m8n8.x4.trans.shared.b16 {%0,%1,%2,%3}, [%4];" \
        : "=r"((r)[0]), "=r"((r)[1]), "=r"((r)[2]), "=r"((r)[3]) : "r"(addr))
#define LDSM_X2T(r, addr) \
    asm volatile("ldmatrix.sync.aligned.m8n8.x2.trans.shared.b16 {%0,%1}, [%2];" \
        : "=r"((r)[0]), "=r"((r)[1]) : "r"(addr))

__device__ __forceinline__ void cpa_wait(int keep) {
    if (keep <= 0)      asm volatile("cp.async.wait_group 0;" ::);
    else                asm volatile("cp.async.wait_group 1;" ::);
}

// =================== FP16 GEMM, 128x128 tile (256 thr) ======================
template <int EPI, int BN_, bool HOUT>
__global__ __launch_bounds__(256, 2) void tgemm_h(
    const __half* __restrict__ A, const __half* __restrict__ B,
    void* __restrict__ Cv, int M, int N, int K)
{
    constexpr int AST = 72;
    constexpr int BST = BN_ + 8;
    constexpr int SA_H = 128 * AST;
    constexpr int SB_H = 64 * BST;
    constexpr int STAGE_H = SA_H + SB_H;
    constexpr int CPR = BN_ / 8;
    constexpr int BITER = (64 * CPR) / 256;
    constexpr int NT = BN_ / 32;

    extern __shared__ __half smh[];
    const int tid = threadIdx.x;
    const int lane = tid & 31, wid = tid >> 5;
    const int gid = lane >> 2, tg = lane & 3;
    const int wm = (wid >> 2) * 64;
    const int wn = (wid & 3) * (BN_ / 4);
    const int bm = blockIdx.y << 7;
    const int bn = blockIdx.x * BN_;
    const uint32_t smu = (uint32_t)__cvta_generic_to_shared(smh);
    const int KT = K >> 6;

    const int arow = lane & 15;
    const int acol = (lane >> 4) << 3;

    auto fill = [&](int kt) {
        const uint32_t sa = smu + (uint32_t)((kt % 3) * STAGE_H) * 2u;
        const uint32_t sb = sa + (uint32_t)SA_H * 2u;
#pragma unroll
        for (int i = 0; i < 4; i++) {
            const int idx = tid + (i << 8);
            const int row = idx >> 3, ch = idx & 7;
            const __half* src = A + (size_t)(bm + row) * K + (kt << 6) + (ch << 3);
            asm volatile("cp.async.cg.shared.global [%0], [%1], 16;"
                         :: "r"(sa + (uint32_t)(row * AST + (ch << 3)) * 2u), "l"(src));
        }
#pragma unroll
        for (int i = 0; i < BITER; i++) {
            const int idx = tid + (i << 8);
            const int row = idx / CPR, ch = idx % CPR;
            const __half* src = B + (size_t)((kt << 6) + row) * N + bn + (ch << 3);
            asm volatile("cp.async.cg.shared.global [%0], [%1], 16;"
                         :: "r"(sb + (uint32_t)(row * BST + (ch << 3)) * 2u), "l"(src));
        }
        asm volatile("cp.async.commit_group;");
    };

    float acc[4][NT][4];
#pragma unroll
    for (int i = 0; i < 4; i++)
#pragma unroll
        for (int j = 0; j < NT; j++)
#pragma unroll
            for (int q = 0; q < 4; q++) acc[i][j][q] = 0.f;

    fill(0);
    if (KT > 1) fill(1);

    for (int kt = 0; kt < KT; ++kt) {
        cpa_wait((kt + 1 < KT) ? 1 : 0);
        __syncthreads();
        if (kt + 2 < KT) fill(kt + 2);

        const uint32_t sa = smu + (uint32_t)((kt % 3) * STAGE_H) * 2u;
        const uint32_t sb = sa + (uint32_t)SA_H * 2u;
#pragma unroll
        for (int ks = 0; ks < 4; ++ks) {
            const int k0 = ks << 4;
            uint32_t af[4][4], bf[NT][2];
#pragma unroll
            for (int mt = 0; mt < 4; mt++)
                LDSM_X4(af[mt], sa + (uint32_t)((wm + mt * 16 + arow) * AST + k0 + acol) * 2u);
            const int krow = k0 + (lane & 7) + ((lane >> 3) & 1) * 8;
#pragma unroll
            for (int nt = 0; nt < NT; nt++)
                LDSM_X2T(bf[nt], sb + (uint32_t)(krow * BST + wn + nt * 8) * 2u);
#pragma unroll
            for (int mt = 0; mt < 4; mt++)
#pragma unroll
                for (int nt = 0; nt < NT; nt++)
                    MMA_F16(acc[mt][nt], af[mt][0], af[mt][1], af[mt][2], af[mt][3],
                            bf[nt][0], bf[nt][1]);
        }
    }

#pragma unroll
    for (int mt = 0; mt < 4; mt++) {
#pragma unroll
        for (int nt = 0; nt < NT; nt++) {
            const int r0 = bm + wm + mt * 16 + gid;
            const int c = bn + wn + nt * 8 + 2 * tg;
            float e0 = epilogue<EPI>(acc[mt][nt][0]);
            float e1 = epilogue<EPI>(acc[mt][nt][1]);
            float e2 = epilogue<EPI>(acc[mt][nt][2]);
            float e3 = epilogue<EPI>(acc[mt][nt][3]);
            if (HOUT) {
                __half* C = (__half*)Cv;
                *(__half2*)(C + (size_t)r0 * N + c) = __floats2half2_rn(e0, e1);
                *(__half2*)(C + (size_t)(r0 + 8) * N + c) = __floats2half2_rn(e2, e3);
            } else {
                float* C = (float*)Cv;
                *(float2*)(C + (size_t)r0 * N + c) = make_float2(e0, e1);
                *(float2*)(C + (size_t)(r0 + 8) * N + c) = make_float2(e2, e3);
            }
        }
    }
}

// =================== FP16 GEMM, 128x256 tile (512 thr) ======================
// 16 warps in 2(m) x 8(n); warp tile 64x32 — same inner loop as tgemm_h.
template <int EPI, bool HOUT>
__global__ __launch_bounds__(512, 1) void tgemm_w(
    const __half* __restrict__ A, const __half* __restrict__ B,
    void* __restrict__ Cv, int M, int N, int K)
{
    constexpr int AST = 72;
    constexpr int BST = 264;                 // 256 + 8
    constexpr int SA_H = 128 * AST;          // 9216
    constexpr int SB_H = 64 * BST;           // 16896
    constexpr int STAGE_H = SA_H + SB_H;     // 26112 halves

    extern __shared__ __half smh[];
    const int tid = threadIdx.x;
    const int lane = tid & 31, wid = tid >> 5;
    const int gid = lane >> 2, tg = lane & 3;
    const int wm = (wid >> 3) * 64;          // 0 or 64
    const int wn = (wid & 7) * 32;           // 0..224
    const int bm = blockIdx.y << 7;
    const int bn = blockIdx.x << 8;
    const uint32_t smu = (uint32_t)__cvta_generic_to_shared(smh);
    const int KT = K >> 6;

    const int arow = lane & 15;
    const int acol = (lane >> 4) << 3;

    auto fill = [&](int kt) {
        const uint32_t sa = smu + (uint32_t)((kt % 3) * STAGE_H) * 2u;
        const uint32_t sb = sa + (uint32_t)SA_H * 2u;
#pragma unroll
        for (int i = 0; i < 2; i++) {        // A: 1024 chunks / 512 thr
            const int idx = tid + (i << 9);
            const int row = idx >> 3, ch = idx & 7;
            const __half* src = A + (size_t)(bm + row) * K + (kt << 6) + (ch << 3);
            asm volatile("cp.async.cg.shared.global [%0], [%1], 16;"
                         :: "r"(sa + (uint32_t)(row * AST + (ch << 3)) * 2u), "l"(src));
        }
#pragma unroll
        for (int i = 0; i < 4; i++) {        // B: 64 rows x 32 chunks
            const int idx = tid + (i << 9);
            const int row = idx >> 5, ch = idx & 31;
            const __half* src = B + (size_t)((kt << 6) + row) * N + bn + (ch << 3);
            asm volatile("cp.async.cg.shared.global [%0], [%1], 16;"
                         :: "r"(sb + (uint32_t)(row * BST + (ch << 3)) * 2u), "l"(src));
        }
        asm volatile("cp.async.commit_group;");
    };

    float acc[4][4][4];
#pragma unroll
    for (int i = 0; i < 4; i++)
#pragma unroll
        for (int j = 0; j < 4; j++)
#pragma unroll
            for (int q = 0; q < 4; q++) acc[i][j][q] = 0.f;

    fill(0);
    if (KT > 1) fill(1);

    for (int kt = 0; kt < KT; ++kt) {
        cpa_wait((kt + 1 < KT) ? 1 : 0);
        __syncthreads();
        if (kt + 2 < KT) fill(kt + 2);

        const uint32_t sa = smu + (uint32_t)((kt % 3) * STAGE_H) * 2u;
        const uint32_t sb = sa + (uint32_t)SA_H * 2u;
#pragma unroll
        for (int ks = 0; ks < 4; ++ks) {
            const int k0 = ks << 4;
            uint32_t af[4][4], bf[4][2];
#pragma unroll
            for (int mt = 0; mt < 4; mt++)
                LDSM_X4(af[mt], sa + (uint32_t)((wm + mt * 16 + arow) * AST + k0 + acol) * 2u);
            const int krow = k0 + (lane & 7) + ((lane >> 3) & 1) * 8;
#pragma unroll
            for (int nt = 0; nt < 4; nt++)
                LDSM_X2T(bf[nt], sb + (uint32_t)(krow * BST + wn + nt * 8) * 2u);
#pragma unroll
            for (int mt = 0; mt < 4; mt++)
#pragma unroll
                for (int nt = 0; nt < 4; nt++)
                    MMA_F16(acc[mt][nt], af[mt][0], af[mt][1], af[mt][2], af[mt][3],
                            bf[nt][0], bf[nt][1]);
        }
    }

#pragma unroll
    for (int mt = 0; mt < 4; mt++) {
#pragma unroll
        for (int nt = 0; nt < 4; nt++) {
            const int r0 = bm + wm + mt * 16 + gid;
            const int c = bn + wn + nt * 8 + 2 * tg;
            float e0 = epilogue<EPI>(acc[mt][nt][0]);
            float e1 = epilogue<EPI>(acc[mt][nt][1]);
            float e2 = epilogue<EPI>(acc[mt][nt][2]);
            float e3 = epilogue<EPI>(acc[mt][nt][3]);
            if (HOUT) {
                __half* C = (__half*)Cv;
                *(__half2*)(C + (size_t)r0 * N + c) = __floats2half2_rn(e0, e1);
                *(__half2*)(C + (size_t)(r0 + 8) * N + c) = __floats2half2_rn(e2, e3);
            } else {
                float* C = (float*)Cv;
                *(float2*)(C + (size_t)r0 * N + c) = make_float2(e0, e1);
                *(float2*)(C + (size_t)(r0 + 8) * N + c) = make_float2(e2, e3);
            }
        }
    }
}

// ---------------- prep: fp32 -> fp16 converts --------------------------------
__global__ __launch_bounds__(256) void cvt_half_k(
    const float4* __restrict__ in, __half* __restrict__ out)
{
    const int i = blockIdx.x * 256 + threadIdx.x;
    float4 v = in[i];
    __half2* o = (__half2*)(out + (size_t)i * 4);
    o[0] = __floats2half2_rn(v.x, v.y);
    o[1] = __floats2half2_rn(v.z, v.w);
}

// W [1024][1024] fp32 -> dst[k][off + n] within [1024][3072] half
__global__ __launch_bounds__(256) void cvt_qkv_k(
    const float* __restrict__ src, __half* __restrict__ dst, int off)
{
    const int i4 = blockIdx.x * 256 + threadIdx.x;     // float4 index
    const int k = i4 >> 8, n4 = (i4 & 255) << 2;
    float4 v = *(const float4*)(src + (size_t)k * 1024 + n4);
    __half2* o = (__half2*)(dst + (size_t)k * QKVN + off + n4);
    o[0] = __floats2half2_rn(v.x, v.y);
    o[1] = __floats2half2_rn(v.z, v.w);
}

// ------------- pass A (fp16 mma): M = K^T diag(lamk) V  [64x64] -------------
__global__ __launch_bounds__(256) void ckv_h_k(
    const __half* __restrict__ QKV, float* __restrict__ Mo)
{
    extern __shared__ char smc[];
    float* dpw = (float*)smc;
    __half* Ks = (__half*)(smc + 544);
    __half* Vs = Ks + 128 * 72;
    const uint32_t smb = (uint32_t)__cvta_generic_to_shared(smc);
    const uint32_t kB = smb + 544;
    const uint32_t vB = kB + 128 * 72 * 2;

    const int c = blockIdx.x, bh = blockIdx.y;
    const int b = bh >> 4, h = bh & 15;
    const int tid = threadIdx.x;
    const int lane = tid & 31, wid = tid >> 5;
    const int gid = lane >> 2, tg = lane & 3;
    const float s = head_slope(h);
    if (tid < 129) dpw[tid] = __expf(-s * (float)tid);
    __syncthreads();

    const size_t rowbase = (size_t)b * 8192 + (size_t)c * 128;
    const int colbase = h * 64;

#pragma unroll
    for (int i = 0; i < 16; ++i) {
        const int idx = tid + (i << 8);
        const int j = idx >> 5, c2 = (idx & 31) << 1;
        const __half2 kv2 = *(const __half2*)(QKV + (rowbase + j) * QKVN + 1024 + colbase + c2);
        const float lk = dpw[127 - j];
        float2 f = __half22float2(kv2);
        *(__half2*)(Ks + j * 72 + c2) = __floats2half2_rn(f.x * lk, f.y * lk);
    }
#pragma unroll
    for (int i = 0; i < 4; ++i) {
        const int idx = tid + (i << 8);
        const int j = idx >> 3, ch = (idx & 7) << 3;
        *(uint4*)(Vs + j * 72 + ch) =
            *(const uint4*)(QKV + (rowbase + j) * QKVN + 2048 + colbase + ch);
    }
    __syncthreads();

    const int wm = (wid >> 2) * 32;
    const int wn = (wid & 3) * 16;
    float acc[2][2][4];
#pragma unroll
    for (int i = 0; i < 2; i++)
#pragma unroll
        for (int j = 0; j < 2; j++)
#pragma unroll
            for (int q = 0; q < 4; q++) acc[i][j][q] = 0.f;

#pragma unroll
    for (int ks = 0; ks < 8; ++ks) {
        const int k0 = ks << 4;
        uint32_t af[2][4], bf[2][2];
        const int akr = k0 + ((lane >> 4) << 3) + (lane & 7);
        const int amc = ((lane >> 3) & 1) << 3;
        const int bkr = k0 + (lane & 7) + (((lane >> 3) & 1) << 3);
#pragma unroll
        for (int mt = 0; mt < 2; mt++)
            LDSM_X4T(af[mt], kB + (uint32_t)(akr * 72 + wm + mt * 16 + amc) * 2u);
#pragma unroll
        for (int nt = 0; nt < 2; nt++)
            LDSM_X2T(bf[nt], vB + (uint32_t)(bkr * 72 + wn + nt * 8) * 2u);
#pragma unroll
        for (int mt = 0; mt < 2; mt++)
#pragma unroll
            for (int nt = 0; nt < 2; nt++)
                MMA_F16(acc[mt][nt], af[mt][0], af[mt][1], af[mt][2], af[mt][3],
                        bf[nt][0], bf[nt][1]);
    }

    float* out = Mo + ((size_t)bh * NCH + c) * 4096;
#pragma unroll
    for (int mt = 0; mt < 2; mt++) {
#pragma unroll
        for (int nt = 0; nt < 2; nt++) {
            const int i0 = wm + mt * 16 + gid;
            const int j0 = wn + nt * 8 + 2 * tg;
            *(float2*)(out + i0 * 64 + j0) = make_float2(acc[mt][nt][0], acc[mt][nt][1]);
            *(float2*)(out + (i0 + 8) * 64 + j0) = make_float2(acc[mt][nt][2], acc[mt][nt][3]);
        }
    }
}

// ------------- pass B: decayed prefix scan of M over chunks -----------------
__global__ __launch_bounds__(256) void kv_scan_k(
    const float* __restrict__ Mi, float* __restrict__ KVo)
{
    const int bh = blockIdx.y;
    const int elem = blockIdx.x * 256 + threadIdx.x;
    const int h = bh & 15;
    const float s = head_slope(h);
    const float lamc = __expf(-s * 128.f);

    float acc = 0.f;
    const size_t base = (size_t)bh * NCH * 4096 + elem;
    for (int c = 0; c < NCH; ++c) {
        const size_t idx = base + (size_t)c * 4096;
        KVo[idx] = acc;
        acc = fmaf(lamc, acc, Mi[idx]);
    }
}

// ------------- pass C (fp16 mma): O = (mask o QK^T) V + lamq o (Q KV) -------
__global__ __launch_bounds__(256) void attn_h_k(
    const __half* __restrict__ QKV, const float* __restrict__ KVi,
    __half* __restrict__ Og)
{
    extern __shared__ char smc[];
    float* dpw = (float*)smc;
    __half* Qs = (__half*)(smc + 544);
    __half* Ks = Qs + 128 * 72;
    __half* KVs = Ks + 128 * 72;
    __half* Ss = KVs + 64 * 72;
    const uint32_t smb = (uint32_t)__cvta_generic_to_shared(smc);
    const uint32_t qB = smb + 544;
    const uint32_t kB = qB + 128 * 72 * 2;
    const uint32_t kvB = kB + 128 * 72 * 2;
    const uint32_t sB = kvB + 64 * 72 * 2;

    const int c = blockIdx.x, bh = blockIdx.y;
    const int b = bh >> 4, h = bh & 15;
    const int tid = threadIdx.x;
    const int lane = tid & 31, wid = tid >> 5;
    const int gid = lane >> 2, tg = lane & 3;
    const int arow = lane & 15;
    const int acol = (lane >> 4) << 3;
    const int brow = lane & 7;
    const int bcol = ((lane >> 3) & 1) << 3;
    const float s = head_slope(h);
    if (tid < 129) dpw[tid] = __expf(-s * (float)tid);

    const size_t rowbase = (size_t)b * 8192 + (size_t)c * 128;
    const int colbase = h * 64;

#pragma unroll
    for (int i = 0; i < 4; ++i) {
        const int idx = tid + (i << 8);
        const int r = idx >> 3, ch = (idx & 7) << 3;
        const size_t g = (rowbase + r) * QKVN + colbase + ch;
        *(uint4*)(Qs + r * 72 + ch) = *(const uint4*)(QKV + g);
        *(uint4*)(Ks + r * 72 + ch) = *(const uint4*)(QKV + g + 1024);
    }
    {
        const float* kvsrc = KVi + ((size_t)bh * NCH + c) * 4096;
#pragma unroll
        for (int i = 0; i < 8; ++i) {
            const int idx = tid + (i << 8);
            const int d = idx >> 5, e2 = (idx & 31) << 1;
            float2 f = *(const float2*)(kvsrc + d * 64 + e2);
            *(__half2*)(KVs + d * 72 + e2) = __floats2half2_rn(f.x, f.y);
        }
    }
    __syncthreads();

    const int wmS = (wid >> 2) * 64, wnS = (wid & 3) * 32;
    const int wnO = (wid & 3) * 16;
    float sc[4][4][4];
    float oc[4][2][4];
#pragma unroll
    for (int i = 0; i < 4; i++) {
#pragma unroll
        for (int j = 0; j < 4; j++)
#pragma unroll
            for (int q = 0; q < 4; q++) sc[i][j][q] = 0.f;
#pragma unroll
        for (int j = 0; j < 2; j++)
#pragma unroll
            for (int q = 0; q < 4; q++) oc[i][j][q] = 0.f;
    }

#pragma unroll
    for (int ks = 0; ks < 4; ++ks) {
        const int k0 = ks << 4;
        uint32_t af[4][4], bf[4][2], bk[2][2];
#pragma unroll
        for (int mt = 0; mt < 4; mt++)
            LDSM_X4(af[mt], qB + (uint32_t)((wmS + mt * 16 + arow) * 72 + k0 + acol) * 2u);
#pragma unroll
        for (int nt = 0; nt < 4; nt++)
            LDSM_X2(bf[nt], kB + (uint32_t)((wnS + nt * 8 + brow) * 72 + k0 + bcol) * 2u);
        const int kvr = k0 + (lane & 7) + (((lane >> 3) & 1) << 3);
#pragma unroll
        for (int nt = 0; nt < 2; nt++)
            LDSM_X2T(bk[nt], kvB + (uint32_t)(kvr * 72 + wnO + nt * 8) * 2u);
#pragma unroll
        for (int mt = 0; mt < 4; mt++) {
#pragma unroll
            for (int nt = 0; nt < 4; nt++)
                MMA_F16(sc[mt][nt], af[mt][0], af[mt][1], af[mt][2], af[mt][3],
                        bf[nt][0], bf[nt][1]);
#pragma unroll
            for (int nt = 0; nt < 2; nt++)
                MMA_F16(oc[mt][nt], af[mt][0], af[mt][1], af[mt][2], af[mt][3],
                        bk[nt][0], bk[nt][1]);
        }
    }

#pragma unroll
    for (int mt = 0; mt < 4; mt++) {
#pragma unroll
        for (int nt = 0; nt < 4; nt++) {
            const int i0 = wmS + mt * 16 + gid;
            const int j0 = wnS + nt * 8 + 2 * tg;
            const int d00 = i0 - j0;
            float v0 = (d00 >= 0) ? sc[mt][nt][0] * dpw[d00] : 0.f;
            float v1 = (d00 >= 1) ? sc[mt][nt][1] * dpw[d00 - 1] : 0.f;
            float v2 = (d00 >= -8) ? sc[mt][nt][2] * dpw[d00 + 8] : 0.f;
            float v3 = (d00 >= -7) ? sc[mt][nt][3] * dpw[d00 + 7] : 0.f;
            *(__half2*)(Ss + i0 * 136 + j0) = __floats2half2_rn(v0, v1);
            *(__half2*)(Ss + (i0 + 8) * 136 + j0) = __floats2half2_rn(v2, v3);
        }
    }

#pragma unroll
    for (int mt = 0; mt < 4; mt++) {
        const int i0 = wmS + mt * 16 + gid;
        const float l0 = dpw[i0 + 1], l1 = dpw[i0 + 9];
#pragma unroll
        for (int nt = 0; nt < 2; nt++) {
            oc[mt][nt][0] *= l0; oc[mt][nt][1] *= l0;
            oc[mt][nt][2] *= l1; oc[mt][nt][3] *= l1;
        }
    }

    __syncthreads();

#pragma unroll
    for (int i = 0; i < 4; ++i) {
        const int idx = tid + (i << 8);
        const int r = idx >> 3, ch = (idx & 7) << 3;
        *(uint4*)(Ks + r * 72 + ch) =
            *(const uint4*)(QKV + (rowbase + r) * QKVN + 2048 + colbase + ch);
    }
    __syncthreads();

#pragma unroll
    for (int ks = 0; ks < 8; ++ks) {
        const int k0 = ks << 4;
        uint32_t af[4][4], bf[2][2];
#pragma unroll
        for (int mt = 0; mt < 4; mt++)
            LDSM_X4(af[mt], sB + (uint32_t)((wmS + mt * 16 + arow) * 136 + k0 + acol) * 2u);
        const int vkr = k0 + (lane & 7) + (((lane >> 3) & 1) << 3);
#pragma unroll
        for (int nt = 0; nt < 2; nt++)
            LDSM_X2T(bf[nt], kB + (uint32_t)(vkr * 72 + wnO + nt * 8) * 2u);
#pragma unroll
        for (int mt = 0; mt < 4; mt++)
#pragma unroll
            for (int nt = 0; nt < 2; nt++)
                MMA_F16(oc[mt][nt], af[mt][0], af[mt][1], af[mt][2], af[mt][3],
                        bf[nt][0], bf[nt][1]);
    }

#pragma unroll
    for (int mt = 0; mt < 4; mt++) {
#pragma unroll
        for (int nt = 0; nt < 2; nt++) {
            const int i0 = wmS + mt * 16 + gid;
            const int e0 = wnO + nt * 8 + 2 * tg;
            *(__half2*)(Og + (rowbase + i0) * 1024 + colbase + e0) =
                __floats2half2_rn(oc[mt][nt][0], oc[mt][nt][1]);
            *(__half2*)(Og + (rowbase + i0 + 8) * 1024 + colbase + e0) =
                __floats2half2_rn(oc[mt][nt][2], oc[mt][nt][3]);
        }
    }
}

// ------------- LayerNorm * gate (half in, half out) -------------------------
__global__ __launch_bounds__(256) void ln_gate_h(
    const __half* __restrict__ O, const __half* __restrict__ G,
    const float* __restrict__ gamma, const float* __restrict__ beta,
    __half* __restrict__ OLN)
{
    __shared__ float red[2][8];
    const int row = blockIdx.x, tid = threadIdx.x;
    const size_t base = (size_t)row * 1024 + (tid << 2);
    float2 a = __half22float2(*(const __half2*)(O + base));
    float2 bb = __half22float2(*(const __half2*)(O + base + 2));
    float sum = a.x + a.y + bb.x + bb.y;
    float sq = a.x * a.x + a.y * a.y + bb.x * bb.x + bb.y * bb.y;
#pragma unroll
    for (int o = 16; o > 0; o >>= 1) {
        sum += __shfl_xor_sync(0xffffffff, sum, o);
        sq += __shfl_xor_sync(0xffffffff, sq, o);
    }
    if ((tid & 31) == 0) { red[0][tid >> 5] = sum; red[1][tid >> 5] = sq; }
    __syncthreads();
    float ts = 0.f, tq = 0.f;
#pragma unroll
    for (int w = 0; w < 8; w++) { ts += red[0][w]; tq += red[1][w]; }
    const float mu = ts * (1.f / 1024.f);
    const float var = tq * (1.f / 1024.f) - mu * mu;
    const float rstd = rsqrtf(var + 1e-5f);

    float4 g4 = *(const float4*)(gamma + (tid << 2));
    float4 b4 = *(const float4*)(beta + (tid << 2));
    float2 gt0 = __half22float2(*(const __half2*)(G + base));
    float2 gt1 = __half22float2(*(const __half2*)(G + base + 2));
    float o0 = ((a.x - mu) * rstd * g4.x + b4.x) * gt0.x;
    float o1 = ((a.y - mu) * rstd * g4.y + b4.y) * gt0.y;
    float o2 = ((bb.x - mu) * rstd * g4.z + b4.z) * gt1.x;
    float o3 = ((bb.y - mu) * rstd * g4.w + b4.w) * gt1.y;
    *(__half2*)(OLN + base) = __floats2half2_rn(o0, o1);
    *(__half2*)(OLN + base + 2) = __floats2half2_rn(o2, o3);
}

// ---------------------------------------------------------------------------
extern "C" void kernel_launch(void* const* d_in, const int* in_sizes, int n_in,
                              void* d_out, int out_size)
{
    const float* x     = (const float*)d_in[0];
    const float* Wq    = (const float*)d_in[1];
    const float* Wk    = (const float*)d_in[2];
    const float* Wv    = (const float*)d_in[3];
    const float* Wo    = (const float*)d_in[4];
    const float* gamma = (const float*)d_in[5];
    const float* beta  = (const float*)d_in[6];
    const float* Wg1   = (const float*)d_in[7];
    const float* Wg2   = (const float*)d_in[8];
    float* out = (float*)d_out;

    void *pX, *pWqkv, *pWo, *pWg1, *pWg2, *pQKV, *pG1, *pGATE, *pO, *pOLN, *pM, *pKV;
    cudaGetSymbolAddress(&pX, hX);
    cudaGetSymbolAddress(&pWqkv, hWqkv);
    cudaGetSymbolAddress(&pWo, hWo);
    cudaGetSymbolAddress(&pWg1, hWg1);
    cudaGetSymbolAddress(&pWg2, hWg2);
    cudaGetSymbolAddress(&pQKV, hQKV);
    cudaGetSymbolAddress(&pG1, hG1);
    cudaGetSymbolAddress(&pGATE, hGATE);
    cudaGetSymbolAddress(&pO, hO);
    cudaGetSymbolAddress(&pOLN, hOLN);
    cudaGetSymbolAddress(&pM, gM);
    cudaGetSymbolAddress(&pKV, gKV);
    __half* X = (__half*)pX;       __half* Wqkv = (__half*)pWqkv;
    __half* WoH = (__half*)pWo;    __half* Wg1H = (__half*)pWg1;
    __half* Wg2H = (__half*)pWg2;  __half* QKV = (__half*)pQKV;
    __half* G1 = (__half*)pG1;     __half* GATE = (__half*)pGATE;
    __half* O = (__half*)pO;       __half* OLN = (__half*)pOLN;
    float* Mb = (float*)pM;        float* KVb = (float*)pKV;

    // smem sizes
    const int smG128 = 3 * (128 * 72 + 64 * 136) * 2;    // 107520
    const int smG64  = 3 * (128 * 72 + 64 * 72) * 2;     //  82944
    const int smW    = 3 * (128 * 72 + 64 * 264) * 2;    // 156672
    const int smAttn = 544 + (128 * 72 + 128 * 72 + 64 * 72 + 128 * 136) * 2;
    const int smCkv  = 544 + (128 * 72 + 128 * 72) * 2;
    cudaFuncSetAttribute(tgemm_w<1, true>,
                         cudaFuncAttributeMaxDynamicSharedMemorySize, smW);
    cudaFuncSetAttribute(tgemm_w<0, false>,
                         cudaFuncAttributeMaxDynamicSharedMemorySize, smW);
    cudaFuncSetAttribute(tgemm_h<2, 128, true>,
                         cudaFuncAttributeMaxDynamicSharedMemorySize, smG128);
    cudaFuncSetAttribute(tgemm_h<0, 64, true>,
                         cudaFuncAttributeMaxDynamicSharedMemorySize, smG64);
    cudaFuncSetAttribute(attn_h_k,
                         cudaFuncAttributeMaxDynamicSharedMemorySize, smAttn);
    cudaFuncSetAttribute(ckv_h_k,
                         cudaFuncAttributeMaxDynamicSharedMemorySize, smCkv);

    cudaStream_t s0 = 0;            // capture (default) stream
    cudaStream_t s1 = g_s1;

    // ---- fork: s1 joins the capture graph ----
    cudaEventRecord(g_evFork, s0);
    cudaStreamWaitEvent(s1, g_evFork, 0);

    dim3 tB(256);

    // s1: weight converts (independent of x)
    cvt_qkv_k<<<1024, 256, 0, s1>>>(Wq, Wqkv, 0);
    cvt_qkv_k<<<1024, 256, 0, s1>>>(Wk, Wqkv, 1024);
    cvt_qkv_k<<<1024, 256, 0, s1>>>(Wv, Wqkv, 2048);
    cudaEventRecord(g_evW, s1);                     // Wqkv ready
    cvt_half_k<<<EDIM * EDIM / 1024, 256, 0, s1>>>((const float4*)Wo, WoH);
    cvt_half_k<<<EDIM * DH / 1024, 256, 0, s1>>>((const float4*)Wg1, Wg1H);
    cvt_half_k<<<EDIM * DH / 1024, 256, 0, s1>>>((const float4*)Wg2, Wg2H);

    // s0: convert x
    cvt_half_k<<<MDIM * EDIM / 1024, 256, 0, s0>>>((const float4*)x, X);
    cudaEventRecord(g_evX, s0);                     // X ready

    // s1: gate path (needs X)
    cudaStreamWaitEvent(s1, g_evX, 0);
    tgemm_h<0, 64, true><<<dim3(1, MDIM / 128), tB, smG64, s1>>>(
        X, Wg1H, G1, MDIM, DH, EDIM);
    tgemm_h<2, 128, true><<<dim3(EDIM / 128, MDIM / 128), tB, smG128, s1>>>(
        G1, Wg2H, GATE, MDIM, EDIM, DH);
    cudaEventRecord(g_evGate, s1);                  // GATE + WoH ready

    // s0: main chain (128x256 GEMM, 512 threads)
    cudaStreamWaitEvent(s0, g_evW, 0);
    tgemm_w<1, true><<<dim3(QKVN / 256, MDIM / 128), 512, smW, s0>>>(
        X, Wqkv, QKV, MDIM, QKVN, EDIM);
    ckv_h_k<<<dim3(NCH, BHN), tB, smCkv, s0>>>(QKV, Mb);
    kv_scan_k<<<dim3(16, BHN), tB, 0, s0>>>(Mb, KVb);
    attn_h_k<<<dim3(NCH, BHN), tB, smAttn, s0>>>(QKV, KVb, O);

    // join: LN needs GATE (and final GEMM needs WoH)
    cudaStreamWaitEvent(s0, g_evGate, 0);
    ln_gate_h<<<MDIM, tB, 0, s0>>>(O, GATE, gamma, beta, OLN);
    tgemm_w<0, false><<<dim3(EDIM / 256, MDIM / 128), 512, smW, s0>>>(
        OLN, WoH, out, MDIM, EDIM, EDIM);
}

// round 14
// speedup vs baseline: 1.0514x; 1.0514x over previous
#include <cuda_runtime.h>
#include <cuda_fp16.h>
#include <math.h>
#include <stdint.h>

// Problem constants
#define MDIM 16384          // B*N = 2*8192 rows
#define EDIM 1024           // embed
#define DH   64             // head dim
#define NCH  64             // chunks per sequence (8192/128)
#define BHN  32             // B*H
#define QKVN 3072           // fused projection width

// ---------------- scratch (device globals) ----------------------------------
__device__ __half hX[MDIM * EDIM];
__device__ __half hWqkv[EDIM * QKVN];     // [k][n] concat Wq|Wk|Wv
__device__ __half hWo[EDIM * EDIM];       // [k][n]
__device__ __half hWg1[EDIM * DH];        // [k][n]
__device__ __half hWg2[DH * EDIM];        // [k][n]
__device__ __half hQKV[MDIM * QKVN];      // fused silu(xW) outputs
__device__ __half hG1[MDIM * DH];
__device__ __half hGATE[MDIM * EDIM];
__device__ __half hO[MDIM * EDIM];
__device__ __half hOLN[MDIM * EDIM];
__device__ float gM[BHN * NCH * DH * DH];
__device__ float gKV[BHN * NCH * DH * DH];

// ---------------- streams/events for graph fork-join (created at load) ------
static cudaStream_t g_s1 = nullptr;
static cudaEvent_t g_evFork = nullptr, g_evW = nullptr, g_evX = nullptr,
                   g_evGate = nullptr;
namespace {
struct StreamInit {
    StreamInit() {
        cudaStreamCreateWithFlags(&g_s1, cudaStreamNonBlocking);
        cudaEventCreateWithFlags(&g_evFork, cudaEventDisableTiming);
        cudaEventCreateWithFlags(&g_evW, cudaEventDisableTiming);
        cudaEventCreateWithFlags(&g_evX, cudaEventDisableTiming);
        cudaEventCreateWithFlags(&g_evGate, cudaEventDisableTiming);
    }
};
StreamInit g_stream_init;
}

__device__ __forceinline__ float head_slope(int h) {
    return exp2f(-0.5f * (float)(h + 1)) * 1.00001f;
}

template <int EPI>
__device__ __forceinline__ float epilogue(float v) {
    if (EPI == 1) {                       // silu (fast-math)
        const float e = __expf(-v);
        return __fdividef(v, 1.f + e);
    }
    if (EPI == 2) {                       // sigmoid (fast-math)
        const float e = __expf(-v);
        return __fdividef(1.f, 1.f + e);
    }
    return v;
}

#define MMA_F16(acc, a0, a1, a2, a3, b0, b1) \
    asm volatile( \
        "mma.sync.aligned.m16n8k16.row.col.f32.f16.f16.f32 " \
        "{%0,%1,%2,%3}, {%4,%5,%6,%7}, {%8,%9}, {%0,%1,%2,%3};\n" \
        : "+f"((acc)[0]), "+f"((acc)[1]), "+f"((acc)[2]), "+f"((acc)[3]) \
        : "r"(a0), "r"(a1), "r"(a2), "r"(a3), "r"(b0), "r"(b1))

#define LDSM_X4(r, addr) \
    asm volatile("ldmatrix.sync.aligned.m8n8.x4.shared.b16 {%0,%1,%2,%3}, [%4];" \
        : "=r"((r)[0]), "=r"((r)[1]), "=r"((r)[2]), "=r"((r)[3]) : "r"(addr))
#define LDSM_X2(r, addr) \
    asm volatile("ldmatrix.sync.aligned.m8n8.x2.shared.b16 {%0,%1}, [%2];" \
        : "=r"((r)[0]), "=r"((r)[1]) : "r"(addr))
#define LDSM_X4T(r, addr) \
    asm volatile("ldmatrix.sync.aligned.m8n8.x4.trans.shared.b16 {%0,%1,%2,%3}, [%4];" \
        : "=r"((r)[0]), "=r"((r)[1]), "=r"((r)[2]), "=r"((r)[3]) : "r"(addr))
#define LDSM_X2T(r, addr) \
    asm volatile("ldmatrix.sync.aligned.m8n8.x2.trans.shared.b16 {%0,%1}, [%2];" \
        : "=r"((r)[0]), "=r"((r)[1]) : "r"(addr))

__device__ __forceinline__ void cpa_wait(int keep) {
    if (keep <= 0)      asm volatile("cp.async.wait_group 0;" ::);
    else                asm volatile("cp.async.wait_group 1;" ::);
}

// =================== FP16 GEMM, 128x128 tile (256 thr) ======================
// CTA raster swizzle: groups of 8 m-tiles share B columns in one wave.
template <int EPI, int BN_, bool HOUT>
__global__ __launch_bounds__(256, 2) void tgemm_h(
    const __half* __restrict__ A, const __half* __restrict__ B,
    void* __restrict__ Cv, int M, int N, int K)
{
    constexpr int AST = 72;
    constexpr int BST = BN_ + 8;
    constexpr int SA_H = 128 * AST;
    constexpr int SB_H = 64 * BST;
    constexpr int STAGE_H = SA_H + SB_H;
    constexpr int CPR = BN_ / 8;
    constexpr int BITER = (64 * CPR) / 256;
    constexpr int NT = BN_ / 32;

    extern __shared__ __half smh[];
    const int tid = threadIdx.x;
    const int lane = tid & 31, wid = tid >> 5;
    const int gid = lane >> 2, tg = lane & 3;
    const int wm = (wid >> 2) * 64;
    const int wn = (wid & 3) * (BN_ / 4);

    // ---- CTA swizzle (bijection on block indices) ----
    int bm, bn;
    {
        const int gx = gridDim.x, gy = gridDim.y;
        const int pid = blockIdx.y * gx + blockIdx.x;
        const int GROUP = 8;
        const int span = GROUP * gx;
        const int group = pid / span;
        const int first = group * GROUP;
        const int rem = gy - first;
        const int gsz = rem < GROUP ? rem : GROUP;
        const int loc = pid - group * span;
        bm = (first + loc % gsz) << 7;
        bn = (loc / gsz) * BN_;
    }

    const uint32_t smu = (uint32_t)__cvta_generic_to_shared(smh);
    const int KT = K >> 6;

    const int arow = lane & 15;
    const int acol = (lane >> 4) << 3;

    auto fill = [&](int kt) {
        const uint32_t sa = smu + (uint32_t)((kt % 3) * STAGE_H) * 2u;
        const uint32_t sb = sa + (uint32_t)SA_H * 2u;
#pragma unroll
        for (int i = 0; i < 4; i++) {
            const int idx = tid + (i << 8);
            const int row = idx >> 3, ch = idx & 7;
            const __half* src = A + (size_t)(bm + row) * K + (kt << 6) + (ch << 3);
            asm volatile("cp.async.cg.shared.global [%0], [%1], 16;"
                         :: "r"(sa + (uint32_t)(row * AST + (ch << 3)) * 2u), "l"(src));
        }
#pragma unroll
        for (int i = 0; i < BITER; i++) {
            const int idx = tid + (i << 8);
            const int row = idx / CPR, ch = idx % CPR;
            const __half* src = B + (size_t)((kt << 6) + row) * N + bn + (ch << 3);
            asm volatile("cp.async.cg.shared.global [%0], [%1], 16;"
                         :: "r"(sb + (uint32_t)(row * BST + (ch << 3)) * 2u), "l"(src));
        }
        asm volatile("cp.async.commit_group;");
    };

    float acc[4][NT][4];
#pragma unroll
    for (int i = 0; i < 4; i++)
#pragma unroll
        for (int j = 0; j < NT; j++)
#pragma unroll
            for (int q = 0; q < 4; q++) acc[i][j][q] = 0.f;

    fill(0);
    if (KT > 1) fill(1);

    for (int kt = 0; kt < KT; ++kt) {
        cpa_wait((kt + 1 < KT) ? 1 : 0);
        __syncthreads();
        if (kt + 2 < KT) fill(kt + 2);

        const uint32_t sa = smu + (uint32_t)((kt % 3) * STAGE_H) * 2u;
        const uint32_t sb = sa + (uint32_t)SA_H * 2u;
#pragma unroll
        for (int ks = 0; ks < 4; ++ks) {
            const int k0 = ks << 4;
            uint32_t af[4][4], bf[NT][2];
#pragma unroll
            for (int mt = 0; mt < 4; mt++)
                LDSM_X4(af[mt], sa + (uint32_t)((wm + mt * 16 + arow) * AST + k0 + acol) * 2u);
            const int krow = k0 + (lane & 7) + ((lane >> 3) & 1) * 8;
#pragma unroll
            for (int nt = 0; nt < NT; nt++)
                LDSM_X2T(bf[nt], sb + (uint32_t)(krow * BST + wn + nt * 8) * 2u);
#pragma unroll
            for (int mt = 0; mt < 4; mt++)
#pragma unroll
                for (int nt = 0; nt < NT; nt++)
                    MMA_F16(acc[mt][nt], af[mt][0], af[mt][1], af[mt][2], af[mt][3],
                            bf[nt][0], bf[nt][1]);
        }
    }

#pragma unroll
    for (int mt = 0; mt < 4; mt++) {
#pragma unroll
        for (int nt = 0; nt < NT; nt++) {
            const int r0 = bm + wm + mt * 16 + gid;
            const int c = bn + wn + nt * 8 + 2 * tg;
            float e0 = epilogue<EPI>(acc[mt][nt][0]);
            float e1 = epilogue<EPI>(acc[mt][nt][1]);
            float e2 = epilogue<EPI>(acc[mt][nt][2]);
            float e3 = epilogue<EPI>(acc[mt][nt][3]);
            if (HOUT) {
                __half* C = (__half*)Cv;
                *(__half2*)(C + (size_t)r0 * N + c) = __floats2half2_rn(e0, e1);
                *(__half2*)(C + (size_t)(r0 + 8) * N + c) = __floats2half2_rn(e2, e3);
            } else {
                float* C = (float*)Cv;
                *(float2*)(C + (size_t)r0 * N + c) = make_float2(e0, e1);
                *(float2*)(C + (size_t)(r0 + 8) * N + c) = make_float2(e2, e3);
            }
        }
    }
}

// ---------------- prep: fp32 -> fp16 converts --------------------------------
__global__ __launch_bounds__(256) void cvt_half_k(
    const float4* __restrict__ in, __half* __restrict__ out)
{
    const int i = blockIdx.x * 256 + threadIdx.x;
    float4 v = in[i];
    __half2* o = (__half2*)(out + (size_t)i * 4);
    o[0] = __floats2half2_rn(v.x, v.y);
    o[1] = __floats2half2_rn(v.z, v.w);
}

// W [1024][1024] fp32 -> dst[k][off + n] within [1024][3072] half
__global__ __launch_bounds__(256) void cvt_qkv_k(
    const float* __restrict__ src, __half* __restrict__ dst, int off)
{
    const int i4 = blockIdx.x * 256 + threadIdx.x;     // float4 index
    const int k = i4 >> 8, n4 = (i4 & 255) << 2;
    float4 v = *(const float4*)(src + (size_t)k * 1024 + n4);
    __half2* o = (__half2*)(dst + (size_t)k * QKVN + off + n4);
    o[0] = __floats2half2_rn(v.x, v.y);
    o[1] = __floats2half2_rn(v.z, v.w);
}

// ------------- pass A (fp16 mma): M = K^T diag(lamk) V  [64x64] -------------
__global__ __launch_bounds__(256) void ckv_h_k(
    const __half* __restrict__ QKV, float* __restrict__ Mo)
{
    extern __shared__ char smc[];
    float* dpw = (float*)smc;
    __half* Ks = (__half*)(smc + 544);
    __half* Vs = Ks + 128 * 72;
    const uint32_t smb = (uint32_t)__cvta_generic_to_shared(smc);
    const uint32_t kB = smb + 544;
    const uint32_t vB = kB + 128 * 72 * 2;

    const int c = blockIdx.x, bh = blockIdx.y;
    const int b = bh >> 4, h = bh & 15;
    const int tid = threadIdx.x;
    const int lane = tid & 31, wid = tid >> 5;
    const int gid = lane >> 2, tg = lane & 3;
    const float s = head_slope(h);
    if (tid < 129) dpw[tid] = __expf(-s * (float)tid);
    __syncthreads();

    const size_t rowbase = (size_t)b * 8192 + (size_t)c * 128;
    const int colbase = h * 64;

#pragma unroll
    for (int i = 0; i < 16; ++i) {
        const int idx = tid + (i << 8);
        const int j = idx >> 5, c2 = (idx & 31) << 1;
        const __half2 kv2 = *(const __half2*)(QKV + (rowbase + j) * QKVN + 1024 + colbase + c2);
        const float lk = dpw[127 - j];
        float2 f = __half22float2(kv2);
        *(__half2*)(Ks + j * 72 + c2) = __floats2half2_rn(f.x * lk, f.y * lk);
    }
#pragma unroll
    for (int i = 0; i < 4; ++i) {
        const int idx = tid + (i << 8);
        const int j = idx >> 3, ch = (idx & 7) << 3;
        *(uint4*)(Vs + j * 72 + ch) =
            *(const uint4*)(QKV + (rowbase + j) * QKVN + 2048 + colbase + ch);
    }
    __syncthreads();

    const int wm = (wid >> 2) * 32;
    const int wn = (wid & 3) * 16;
    float acc[2][2][4];
#pragma unroll
    for (int i = 0; i < 2; i++)
#pragma unroll
        for (int j = 0; j < 2; j++)
#pragma unroll
            for (int q = 0; q < 4; q++) acc[i][j][q] = 0.f;

#pragma unroll
    for (int ks = 0; ks < 8; ++ks) {
        const int k0 = ks << 4;
        uint32_t af[2][4], bf[2][2];
        const int akr = k0 + ((lane >> 4) << 3) + (lane & 7);
        const int amc = ((lane >> 3) & 1) << 3;
        const int bkr = k0 + (lane & 7) + (((lane >> 3) & 1) << 3);
#pragma unroll
        for (int mt = 0; mt < 2; mt++)
            LDSM_X4T(af[mt], kB + (uint32_t)(akr * 72 + wm + mt * 16 + amc) * 2u);
#pragma unroll
        for (int nt = 0; nt < 2; nt++)
            LDSM_X2T(bf[nt], vB + (uint32_t)(bkr * 72 + wn + nt * 8) * 2u);
#pragma unroll
        for (int mt = 0; mt < 2; mt++)
#pragma unroll
            for (int nt = 0; nt < 2; nt++)
                MMA_F16(acc[mt][nt], af[mt][0], af[mt][1], af[mt][2], af[mt][3],
                        bf[nt][0], bf[nt][1]);
    }

    float* out = Mo + ((size_t)bh * NCH + c) * 4096;
#pragma unroll
    for (int mt = 0; mt < 2; mt++) {
#pragma unroll
        for (int nt = 0; nt < 2; nt++) {
            const int i0 = wm + mt * 16 + gid;
            const int j0 = wn + nt * 8 + 2 * tg;
            *(float2*)(out + i0 * 64 + j0) = make_float2(acc[mt][nt][0], acc[mt][nt][1]);
            *(float2*)(out + (i0 + 8) * 64 + j0) = make_float2(acc[mt][nt][2], acc[mt][nt][3]);
        }
    }
}

// ------------- pass B: decayed prefix scan of M over chunks -----------------
__global__ __launch_bounds__(256) void kv_scan_k(
    const float* __restrict__ Mi, float* __restrict__ KVo)
{
    const int bh = blockIdx.y;
    const int elem = blockIdx.x * 256 + threadIdx.x;
    const int h = bh & 15;
    const float s = head_slope(h);
    const float lamc = __expf(-s * 128.f);

    float acc = 0.f;
    const size_t base = (size_t)bh * NCH * 4096 + elem;
    for (int c = 0; c < NCH; ++c) {
        const size_t idx = base + (size_t)c * 4096;
        KVo[idx] = acc;
        acc = fmaf(lamc, acc, Mi[idx]);
    }
}

// ------------- pass C (fp16 mma): O = (mask o QK^T) V + lamq o (Q KV) -------
__global__ __launch_bounds__(256) void attn_h_k(
    const __half* __restrict__ QKV, const float* __restrict__ KVi,
    __half* __restrict__ Og)
{
    extern __shared__ char smc[];
    float* dpw = (float*)smc;
    __half* Qs = (__half*)(smc + 544);
    __half* Ks = Qs + 128 * 72;
    __half* KVs = Ks + 128 * 72;
    __half* Ss = KVs + 64 * 72;
    const uint32_t smb = (uint32_t)__cvta_generic_to_shared(smc);
    const uint32_t qB = smb + 544;
    const uint32_t kB = qB + 128 * 72 * 2;
    const uint32_t kvB = kB + 128 * 72 * 2;
    const uint32_t sB = kvB + 64 * 72 * 2;

    const int c = blockIdx.x, bh = blockIdx.y;
    const int b = bh >> 4, h = bh & 15;
    const int tid = threadIdx.x;
    const int lane = tid & 31, wid = tid >> 5;
    const int gid = lane >> 2, tg = lane & 3;
    const int arow = lane & 15;
    const int acol = (lane >> 4) << 3;
    const int brow = lane & 7;
    const int bcol = ((lane >> 3) & 1) << 3;
    const float s = head_slope(h);
    if (tid < 129) dpw[tid] = __expf(-s * (float)tid);

    const size_t rowbase = (size_t)b * 8192 + (size_t)c * 128;
    const int colbase = h * 64;

#pragma unroll
    for (int i = 0; i < 4; ++i) {
        const int idx = tid + (i << 8);
        const int r = idx >> 3, ch = (idx & 7) << 3;
        const size_t g = (rowbase + r) * QKVN + colbase + ch;
        *(uint4*)(Qs + r * 72 + ch) = *(const uint4*)(QKV + g);
        *(uint4*)(Ks + r * 72 + ch) = *(const uint4*)(QKV + g + 1024);
    }
    {
        const float* kvsrc = KVi + ((size_t)bh * NCH + c) * 4096;
#pragma unroll
        for (int i = 0; i < 8; ++i) {
            const int idx = tid + (i << 8);
            const int d = idx >> 5, e2 = (idx & 31) << 1;
            float2 f = *(const float2*)(kvsrc + d * 64 + e2);
            *(__half2*)(KVs + d * 72 + e2) = __floats2half2_rn(f.x, f.y);
        }
    }
    __syncthreads();

    const int wmS = (wid >> 2) * 64, wnS = (wid & 3) * 32;
    const int wnO = (wid & 3) * 16;
    float sc[4][4][4];
    float oc[4][2][4];
#pragma unroll
    for (int i = 0; i < 4; i++) {
#pragma unroll
        for (int j = 0; j < 4; j++)
#pragma unroll
            for (int q = 0; q < 4; q++) sc[i][j][q] = 0.f;
#pragma unroll
        for (int j = 0; j < 2; j++)
#pragma unroll
            for (int q = 0; q < 4; q++) oc[i][j][q] = 0.f;
    }

#pragma unroll
    for (int ks = 0; ks < 4; ++ks) {
        const int k0 = ks << 4;
        uint32_t af[4][4], bf[4][2], bk[2][2];
#pragma unroll
        for (int mt = 0; mt < 4; mt++)
            LDSM_X4(af[mt], qB + (uint32_t)((wmS + mt * 16 + arow) * 72 + k0 + acol) * 2u);
#pragma unroll
        for (int nt = 0; nt < 4; nt++)
            LDSM_X2(bf[nt], kB + (uint32_t)((wnS + nt * 8 + brow) * 72 + k0 + bcol) * 2u);
        const int kvr = k0 + (lane & 7) + (((lane >> 3) & 1) << 3);
#pragma unroll
        for (int nt = 0; nt < 2; nt++)
            LDSM_X2T(bk[nt], kvB + (uint32_t)(kvr * 72 + wnO + nt * 8) * 2u);
#pragma unroll
        for (int mt = 0; mt < 4; mt++) {
#pragma unroll
            for (int nt = 0; nt < 4; nt++)
                MMA_F16(sc[mt][nt], af[mt][0], af[mt][1], af[mt][2], af[mt][3],
                        bf[nt][0], bf[nt][1]);
#pragma unroll
            for (int nt = 0; nt < 2; nt++)
                MMA_F16(oc[mt][nt], af[mt][0], af[mt][1], af[mt][2], af[mt][3],
                        bk[nt][0], bk[nt][1]);
        }
    }

#pragma unroll
    for (int mt = 0; mt < 4; mt++) {
#pragma unroll
        for (int nt = 0; nt < 4; nt++) {
            const int i0 = wmS + mt * 16 + gid;
            const int j0 = wnS + nt * 8 + 2 * tg;
            const int d00 = i0 - j0;
            float v0 = (d00 >= 0) ? sc[mt][nt][0] * dpw[d00] : 0.f;
            float v1 = (d00 >= 1) ? sc[mt][nt][1] * dpw[d00 - 1] : 0.f;
            float v2 = (d00 >= -8) ? sc[mt][nt][2] * dpw[d00 + 8] : 0.f;
            float v3 = (d00 >= -7) ? sc[mt][nt][3] * dpw[d00 + 7] : 0.f;
            *(__half2*)(Ss + i0 * 136 + j0) = __floats2half2_rn(v0, v1);
            *(__half2*)(Ss + (i0 + 8) * 136 + j0) = __floats2half2_rn(v2, v3);
        }
    }

#pragma unroll
    for (int mt = 0; mt < 4; mt++) {
        const int i0 = wmS + mt * 16 + gid;
        const float l0 = dpw[i0 + 1], l1 = dpw[i0 + 9];
#pragma unroll
        for (int nt = 0; nt < 2; nt++) {
            oc[mt][nt][0] *= l0; oc[mt][nt][1] *= l0;
            oc[mt][nt][2] *= l1; oc[mt][nt][3] *= l1;
        }
    }

    __syncthreads();

#pragma unroll
    for (int i = 0; i < 4; ++i) {
        const int idx = tid + (i << 8);
        const int r = idx >> 3, ch = (idx & 7) << 3;
        *(uint4*)(Ks + r * 72 + ch) =
            *(const uint4*)(QKV + (rowbase + r) * QKVN + 2048 + colbase + ch);
    }
    __syncthreads();

#pragma unroll
    for (int ks = 0; ks < 8; ++ks) {
        const int k0 = ks << 4;
        uint32_t af[4][4], bf[2][2];
#pragma unroll
        for (int mt = 0; mt < 4; mt++)
            LDSM_X4(af[mt], sB + (uint32_t)((wmS + mt * 16 + arow) * 136 + k0 + acol) * 2u);
        const int vkr = k0 + (lane & 7) + (((lane >> 3) & 1) << 3);
#pragma unroll
        for (int nt = 0; nt < 2; nt++)
            LDSM_X2T(bf[nt], kB + (uint32_t)(vkr * 72 + wnO + nt * 8) * 2u);
#pragma unroll
        for (int mt = 0; mt < 4; mt++)
#pragma unroll
            for (int nt = 0; nt < 2; nt++)
                MMA_F16(oc[mt][nt], af[mt][0], af[mt][1], af[mt][2], af[mt][3],
                        bf[nt][0], bf[nt][1]);
    }

#pragma unroll
    for (int mt = 0; mt < 4; mt++) {
#pragma unroll
        for (int nt = 0; nt < 2; nt++) {
            const int i0 = wmS + mt * 16 + gid;
            const int e0 = wnO + nt * 8 + 2 * tg;
            *(__half2*)(Og + (rowbase + i0) * 1024 + colbase + e0) =
                __floats2half2_rn(oc[mt][nt][0], oc[mt][nt][1]);
            *(__half2*)(Og + (rowbase + i0 + 8) * 1024 + colbase + e0) =
                __floats2half2_rn(oc[mt][nt][2], oc[mt][nt][3]);
        }
    }
}

// ------------- LayerNorm * gate (half in, half out) -------------------------
__global__ __launch_bounds__(256) void ln_gate_h(
    const __half* __restrict__ O, const __half* __restrict__ G,
    const float* __restrict__ gamma, const float* __restrict__ beta,
    __half* __restrict__ OLN)
{
    __shared__ float red[2][8];
    const int row = blockIdx.x, tid = threadIdx.x;
    const size_t base = (size_t)row * 1024 + (tid << 2);
    float2 a = __half22float2(*(const __half2*)(O + base));
    float2 bb = __half22float2(*(const __half2*)(O + base + 2));
    float sum = a.x + a.y + bb.x + bb.y;
    float sq = a.x * a.x + a.y * a.y + bb.x * bb.x + bb.y * bb.y;
#pragma unroll
    for (int o = 16; o > 0; o >>= 1) {
        sum += __shfl_xor_sync(0xffffffff, sum, o);
        sq += __shfl_xor_sync(0xffffffff, sq, o);
    }
    if ((tid & 31) == 0) { red[0][tid >> 5] = sum; red[1][tid >> 5] = sq; }
    __syncthreads();
    float ts = 0.f, tq = 0.f;
#pragma unroll
    for (int w = 0; w < 8; w++) { ts += red[0][w]; tq += red[1][w]; }
    const float mu = ts * (1.f / 1024.f);
    const float var = tq * (1.f / 1024.f) - mu * mu;
    const float rstd = rsqrtf(var + 1e-5f);

    float4 g4 = *(const float4*)(gamma + (tid << 2));
    float4 b4 = *(const float4*)(beta + (tid << 2));
    float2 gt0 = __half22float2(*(const __half2*)(G + base));
    float2 gt1 = __half22float2(*(const __half2*)(G + base + 2));
    float o0 = ((a.x - mu) * rstd * g4.x + b4.x) * gt0.x;
    float o1 = ((a.y - mu) * rstd * g4.y + b4.y) * gt0.y;
    float o2 = ((bb.x - mu) * rstd * g4.z + b4.z) * gt1.x;
    float o3 = ((bb.y - mu) * rstd * g4.w + b4.w) * gt1.y;
    *(__half2*)(OLN + base) = __floats2half2_rn(o0, o1);
    *(__half2*)(OLN + base + 2) = __floats2half2_rn(o2, o3);
}

// ---------------------------------------------------------------------------
extern "C" void kernel_launch(void* const* d_in, const int* in_sizes, int n_in,
                              void* d_out, int out_size)
{
    const float* x     = (const float*)d_in[0];
    const float* Wq    = (const float*)d_in[1];
    const float* Wk    = (const float*)d_in[2];
    const float* Wv    = (const float*)d_in[3];
    const float* Wo    = (const float*)d_in[4];
    const float* gamma = (const float*)d_in[5];
    const float* beta  = (const float*)d_in[6];
    const float* Wg1   = (const float*)d_in[7];
    const float* Wg2   = (const float*)d_in[8];
    float* out = (float*)d_out;

    void *pX, *pWqkv, *pWo, *pWg1, *pWg2, *pQKV, *pG1, *pGATE, *pO, *pOLN, *pM, *pKV;
    cudaGetSymbolAddress(&pX, hX);
    cudaGetSymbolAddress(&pWqkv, hWqkv);
    cudaGetSymbolAddress(&pWo, hWo);
    cudaGetSymbolAddress(&pWg1, hWg1);
    cudaGetSymbolAddress(&pWg2, hWg2);
    cudaGetSymbolAddress(&pQKV, hQKV);
    cudaGetSymbolAddress(&pG1, hG1);
    cudaGetSymbolAddress(&pGATE, hGATE);
    cudaGetSymbolAddress(&pO, hO);
    cudaGetSymbolAddress(&pOLN, hOLN);
    cudaGetSymbolAddress(&pM, gM);
    cudaGetSymbolAddress(&pKV, gKV);
    __half* X = (__half*)pX;       __half* Wqkv = (__half*)pWqkv;
    __half* WoH = (__half*)pWo;    __half* Wg1H = (__half*)pWg1;
    __half* Wg2H = (__half*)pWg2;  __half* QKV = (__half*)pQKV;
    __half* G1 = (__half*)pG1;     __half* GATE = (__half*)pGATE;
    __half* O = (__half*)pO;       __half* OLN = (__half*)pOLN;
    float* Mb = (float*)pM;        float* KVb = (float*)pKV;

    // smem sizes
    const int smG128 = 3 * (128 * 72 + 64 * 136) * 2;   // 107520
    const int smG64  = 3 * (128 * 72 + 64 * 72) * 2;    //  82944
    const int smAttn = 544 + (128 * 72 + 128 * 72 + 64 * 72 + 128 * 136) * 2;
    const int smCkv  = 544 + (128 * 72 + 128 * 72) * 2;
    cudaFuncSetAttribute(tgemm_h<1, 128, true>,
                         cudaFuncAttributeMaxDynamicSharedMemorySize, smG128);
    cudaFuncSetAttribute(tgemm_h<2, 128, true>,
                         cudaFuncAttributeMaxDynamicSharedMemorySize, smG128);
    cudaFuncSetAttribute(tgemm_h<0, 128, false>,
                         cudaFuncAttributeMaxDynamicSharedMemorySize, smG128);
    cudaFuncSetAttribute(tgemm_h<0, 64, true>,
                         cudaFuncAttributeMaxDynamicSharedMemorySize, smG64);
    cudaFuncSetAttribute(attn_h_k,
                         cudaFuncAttributeMaxDynamicSharedMemorySize, smAttn);
    cudaFuncSetAttribute(ckv_h_k,
                         cudaFuncAttributeMaxDynamicSharedMemorySize, smCkv);

    cudaStream_t s0 = 0;            // capture (default) stream
    cudaStream_t s1 = g_s1;

    // ---- fork: s1 joins the capture graph ----
    cudaEventRecord(g_evFork, s0);
    cudaStreamWaitEvent(s1, g_evFork, 0);

    dim3 tB(256);

    // s1: weight converts (independent of x)
    cvt_qkv_k<<<1024, 256, 0, s1>>>(Wq, Wqkv, 0);
    cvt_qkv_k<<<1024, 256, 0, s1>>>(Wk, Wqkv, 1024);
    cvt_qkv_k<<<1024, 256, 0, s1>>>(Wv, Wqkv, 2048);
    cudaEventRecord(g_evW, s1);                     // Wqkv ready
    cvt_half_k<<<EDIM * EDIM / 1024, 256, 0, s1>>>((const float4*)Wo, WoH);
    cvt_half_k<<<EDIM * DH / 1024, 256, 0, s1>>>((const float4*)Wg1, Wg1H);
    cvt_half_k<<<EDIM * DH / 1024, 256, 0, s1>>>((const float4*)Wg2, Wg2H);

    // s0: convert x
    cvt_half_k<<<MDIM * EDIM / 1024, 256, 0, s0>>>((const float4*)x, X);
    cudaEventRecord(g_evX, s0);                     // X ready

    // s1: gate path (needs X)
    cudaStreamWaitEvent(s1, g_evX, 0);
    tgemm_h<0, 64, true><<<dim3(1, MDIM / 128), tB, smG64, s1>>>(
        X, Wg1H, G1, MDIM, DH, EDIM);
    tgemm_h<2, 128, true><<<dim3(EDIM / 128, MDIM / 128), tB, smG128, s1>>>(
        G1, Wg2H, GATE, MDIM, EDIM, DH);
    cudaEventRecord(g_evGate, s1);                  // GATE + WoH ready

    // s0: main chain
    cudaStreamWaitEvent(s0, g_evW, 0);
    tgemm_h<1, 128, true><<<dim3(QKVN / 128, MDIM / 128), tB, smG128, s0>>>(
        X, Wqkv, QKV, MDIM, QKVN, EDIM);
    ckv_h_k<<<dim3(NCH, BHN), tB, smCkv, s0>>>(QKV, Mb);
    kv_scan_k<<<dim3(16, BHN), tB, 0, s0>>>(Mb, KVb);
    attn_h_k<<<dim3(NCH, BHN), tB, smAttn, s0>>>(QKV, KVb, O);

    // join: LN needs GATE (and final GEMM needs WoH)
    cudaStreamWaitEvent(s0, g_evGate, 0);
    ln_gate_h<<<MDIM, tB, 0, s0>>>(O, GATE, gamma, beta, OLN);
    tgemm_h<0, 128, false><<<dim3(EDIM / 128, MDIM / 128), tB, smG128, s0>>>(
        OLN, WoH, out, MDIM, EDIM, EDIM);
}